// round 5
// baseline (speedup 1.0000x reference)
#include <cuda_runtime.h>
#include <cuda_bf16.h>
#include <cuda_fp16.h>
#include <cstdint>

#define N_NODES 50000
#define IN_CH   256
#define HID_CH  64
#define N_EDGES 800000
#define NBINS   N_NODES
#define SCAN_BLOCKS 196   // 196*256 = 50176 >= 50000

#define WT_STRIDE 264     // padded k-stride (bf16 elems) for W^T: conflict-free LDS

// Scratch (device globals; no allocation allowed)
__device__ __align__(16) __half g_xw[N_NODES * HID_CH];        // x @ W, fp16
__device__ __align__(16) __nv_bfloat16 g_WhiT[HID_CH * WT_STRIDE];
__device__ __align__(16) __nv_bfloat16 g_WloT[HID_CH * WT_STRIDE];
__device__ int   g_cnt[NBINS];
__device__ int   g_off[NBINS + 1];
__device__ int   g_cursor[NBINS];
__device__ int   g_bsum[SCAN_BLOCKS];
__device__ int   g_bsum2[SCAN_BLOCKS];
__device__ int   g_sorted_src[N_EDGES];

// ---------------------------------------------------------------------------
// W split: W[k][n] fp32 -> transposed bf16 hi/lo tables W^T[n][k] (padded).
// ---------------------------------------------------------------------------
__global__ void convert_w_kernel(const float* __restrict__ W) {
    int i = blockIdx.x * blockDim.x + threadIdx.x;
    if (i >= IN_CH * HID_CH) return;
    int k = i >> 6, n = i & 63;
    float w = W[i];
    __nv_bfloat16 hi = __float2bfloat16_rn(w);
    float rem = w - __bfloat162float(hi);
    g_WhiT[n * WT_STRIDE + k] = hi;
    g_WloT[n * WT_STRIDE + k] = __float2bfloat16_rn(rem);
}

// ---------------------------------------------------------------------------
// Tensor-core GEMM: g_xw = x @ W via bf16-split mma.sync (3 passes).
// Output stored as fp16 (message compression for the gather).
// ---------------------------------------------------------------------------
#define GEMM_SMEM_BYTES (2 * HID_CH * WT_STRIDE * 2)

__device__ __forceinline__ void mma16816(float d[4], const uint32_t a[4],
                                         uint32_t b0, uint32_t b1) {
    asm volatile(
        "mma.sync.aligned.m16n8k16.row.col.f32.bf16.bf16.f32 "
        "{%0,%1,%2,%3}, {%4,%5,%6,%7}, {%8,%9}, {%0,%1,%2,%3};\n"
        : "+f"(d[0]), "+f"(d[1]), "+f"(d[2]), "+f"(d[3])
        : "r"(a[0]), "r"(a[1]), "r"(a[2]), "r"(a[3]), "r"(b0), "r"(b1));
}

__global__ __launch_bounds__(256, 3)
void gemm_mma_kernel(const float* __restrict__ x) {
    extern __shared__ __align__(16) __nv_bfloat16 sW[];
    __nv_bfloat16* sWhi = sW;
    __nv_bfloat16* sWlo = sW + HID_CH * WT_STRIDE;

    const int tid = threadIdx.x;
    {
        const uint4* shi = (const uint4*)g_WhiT;
        const uint4* slo = (const uint4*)g_WloT;
        uint4* dhi = (uint4*)sWhi;
        uint4* dlo = (uint4*)sWlo;
        const int n16 = HID_CH * WT_STRIDE * 2 / 16;
        for (int i = tid; i < n16; i += 256) { dhi[i] = shi[i]; dlo[i] = slo[i]; }
    }
    __syncthreads();

    const int lane = tid & 31;
    const int warp = tid >> 5;
    const int row0 = blockIdx.x * 128 + warp * 16;
    const int rA   = lane >> 2;
    const int cA   = (lane & 3) * 2;

    int r0 = row0 + rA;     if (r0 > N_NODES - 1) r0 = N_NODES - 1;
    int r1 = row0 + rA + 8; if (r1 > N_NODES - 1) r1 = N_NODES - 1;
    const float* xr0 = x + (size_t)r0 * IN_CH;
    const float* xr1 = x + (size_t)r1 * IN_CH;

    float d[8][4];
    #pragma unroll
    for (int nt = 0; nt < 8; nt++)
        #pragma unroll
        for (int j = 0; j < 4; j++) d[nt][j] = 0.f;

    #pragma unroll 4
    for (int k0 = 0; k0 < IN_CH; k0 += 16) {
        float2 f00 = *(const float2*)(xr0 + k0 + cA);
        float2 f10 = *(const float2*)(xr1 + k0 + cA);
        float2 f01 = *(const float2*)(xr0 + k0 + 8 + cA);
        float2 f11 = *(const float2*)(xr1 + k0 + 8 + cA);

        __nv_bfloat162 h00 = __floats2bfloat162_rn(f00.x, f00.y);
        __nv_bfloat162 h10 = __floats2bfloat162_rn(f10.x, f10.y);
        __nv_bfloat162 h01 = __floats2bfloat162_rn(f01.x, f01.y);
        __nv_bfloat162 h11 = __floats2bfloat162_rn(f11.x, f11.y);

        __nv_bfloat162 l00 = __floats2bfloat162_rn(f00.x - __low2float(h00),
                                                   f00.y - __high2float(h00));
        __nv_bfloat162 l10 = __floats2bfloat162_rn(f10.x - __low2float(h10),
                                                   f10.y - __high2float(h10));
        __nv_bfloat162 l01 = __floats2bfloat162_rn(f01.x - __low2float(h01),
                                                   f01.y - __high2float(h01));
        __nv_bfloat162 l11 = __floats2bfloat162_rn(f11.x - __low2float(h11),
                                                   f11.y - __high2float(h11));

        uint32_t ahi[4] = { *(uint32_t*)&h00, *(uint32_t*)&h10,
                            *(uint32_t*)&h01, *(uint32_t*)&h11 };
        uint32_t alo[4] = { *(uint32_t*)&l00, *(uint32_t*)&l10,
                            *(uint32_t*)&l01, *(uint32_t*)&l11 };

        const int nB = lane >> 2;
        const int kB = (lane & 3) * 2;

        #pragma unroll
        for (int nt = 0; nt < 8; nt++) {
            int base = (nt * 8 + nB) * WT_STRIDE + k0 + kB;
            uint32_t bh0 = *(const uint32_t*)(sWhi + base);
            uint32_t bh1 = *(const uint32_t*)(sWhi + base + 8);
            uint32_t bl0 = *(const uint32_t*)(sWlo + base);
            uint32_t bl1 = *(const uint32_t*)(sWlo + base + 8);
            mma16816(d[nt], ahi, bh0, bh1);
            mma16816(d[nt], ahi, bl0, bl1);
            mma16816(d[nt], alo, bh0, bh1);
        }
    }

    int rr0 = row0 + rA;
    int rr1 = rr0 + 8;
    #pragma unroll
    for (int nt = 0; nt < 8; nt++) {
        int col = nt * 8 + cA;   // even -> 4B-aligned half2 store
        if (rr0 < N_NODES) {
            __half2 h = __floats2half2_rn(d[nt][0], d[nt][1]);
            *(__half2*)(g_xw + (size_t)rr0 * HID_CH + col) = h;
        }
        if (rr1 < N_NODES) {
            __half2 h = __floats2half2_rn(d[nt][2], d[nt][3]);
            *(__half2*)(g_xw + (size_t)rr1 * HID_CH + col) = h;
        }
    }
}

// ---------------------------------------------------------------------------
// CSR build
// ---------------------------------------------------------------------------
__global__ void zero_kernel() {
    int i = blockIdx.x * blockDim.x + threadIdx.x;
    if (i < NBINS) g_cnt[i] = 0;
}

// 4 edges per thread via int4
__global__ void hist_kernel(const int* __restrict__ ei) {
    int e4 = blockIdx.x * blockDim.x + threadIdx.x;
    if (e4 >= N_EDGES / 4) return;
    int4 d = ((const int4*)(ei + N_EDGES))[e4];
    atomicAdd(&g_cnt[d.x], 1);
    atomicAdd(&g_cnt[d.y], 1);
    atomicAdd(&g_cnt[d.z], 1);
    atomicAdd(&g_cnt[d.w], 1);
}

// shfl-based block scan, 256 threads/block
__global__ void scan_a_kernel() {
    int t = threadIdx.x, i = blockIdx.x * 256 + t;
    int lane = t & 31, w = t >> 5;
    int v = (i < NBINS) ? g_cnt[i] : 0;
    int inc = v;
    #pragma unroll
    for (int d = 1; d < 32; d <<= 1) {
        int y = __shfl_up_sync(0xFFFFFFFFu, inc, d);
        if (lane >= d) inc += y;
    }
    __shared__ int ws[8];
    if (lane == 31) ws[w] = inc;
    __syncthreads();
    if (t < 8) {
        int s = ws[t], inc2 = s;
        #pragma unroll
        for (int d = 1; d < 8; d <<= 1) {
            int y = __shfl_up_sync(0xFFu, inc2, d);
            if (t >= d) inc2 += y;
        }
        ws[t] = inc2 - s;   // exclusive warp base
    }
    __syncthreads();
    int excl = inc - v + ws[w];
    if (i < NBINS) g_off[i] = excl;
    if (t == 255) g_bsum[blockIdx.x] = excl + v;   // block total
}

__global__ void scan_b_kernel() {
    int t = threadIdx.x;
    int lane = t & 31, w = t >> 5;
    int v = (t < SCAN_BLOCKS) ? g_bsum[t] : 0;
    int inc = v;
    #pragma unroll
    for (int d = 1; d < 32; d <<= 1) {
        int y = __shfl_up_sync(0xFFFFFFFFu, inc, d);
        if (lane >= d) inc += y;
    }
    __shared__ int ws[8];
    if (lane == 31) ws[w] = inc;
    __syncthreads();
    if (t < 8) {
        int s = ws[t], inc2 = s;
        #pragma unroll
        for (int d = 1; d < 8; d <<= 1) {
            int y = __shfl_up_sync(0xFFu, inc2, d);
            if (t >= d) inc2 += y;
        }
        ws[t] = inc2 - s;
    }
    __syncthreads();
    if (t < SCAN_BLOCKS) g_bsum2[t] = inc - v + ws[w];
}

__global__ void scan_c_kernel() {
    int i = blockIdx.x * blockDim.x + threadIdx.x;
    if (i < NBINS) {
        int off = g_off[i] + g_bsum2[i >> 8];
        g_off[i]    = off;
        g_cursor[i] = off;
    }
    if (i == 0) g_off[NBINS] = N_EDGES;
}

// 4 edges per thread via int4
__global__ void reorder_kernel(const int* __restrict__ ei) {
    int e4 = blockIdx.x * blockDim.x + threadIdx.x;
    if (e4 >= N_EDGES / 4) return;
    int4 s = ((const int4*)ei)[e4];
    int4 d = ((const int4*)(ei + N_EDGES))[e4];
    int p0 = atomicAdd(&g_cursor[d.x], 1);
    int p1 = atomicAdd(&g_cursor[d.y], 1);
    int p2 = atomicAdd(&g_cursor[d.z], 1);
    int p3 = atomicAdd(&g_cursor[d.w], 1);
    g_sorted_src[p0] = s.x;
    g_sorted_src[p1] = s.y;
    g_sorted_src[p2] = s.z;
    g_sorted_src[p3] = s.w;
}

// ---------------------------------------------------------------------------
// Gather-sum (fp16 msgs) + fused bias + PReLU. One warp per dst node.
// slot = lane>>4 (2 edge slots), cg = lane&15 -> channels [cg*4, cg*4+4).
// Each lane loads 4 halfs (8B); 16 lanes cover a 128B row.
// ---------------------------------------------------------------------------
__global__ __launch_bounds__(256)
void gather_kernel(const float* __restrict__ bias,
                   const float* __restrict__ prelu_a,
                   float* __restrict__ out) {
    int warp = (blockIdx.x * blockDim.x + threadIdx.x) >> 5;
    int lane = threadIdx.x & 31;
    if (warp >= N_NODES) return;

    int beg = g_off[warp];
    int end = g_off[warp + 1];
    int slot = lane >> 4;
    int cg   = lane & 15;

    float4 acc = make_float4(0.f, 0.f, 0.f, 0.f);
    for (int i = beg + slot; i < end; i += 2) {
        int src = __ldg(&g_sorted_src[i]);
        uint2 raw = *(const uint2*)(g_xw + (size_t)src * HID_CH + cg * 4);
        float2 lo = __half22float2(*(__half2*)&raw.x);
        float2 hi = __half22float2(*(__half2*)&raw.y);
        acc.x += lo.x; acc.y += lo.y; acc.z += hi.x; acc.w += hi.y;
    }

    acc.x += __shfl_xor_sync(0xFFFFFFFFu, acc.x, 16);
    acc.y += __shfl_xor_sync(0xFFFFFFFFu, acc.y, 16);
    acc.z += __shfl_xor_sync(0xFFFFFFFFu, acc.z, 16);
    acc.w += __shfl_xor_sync(0xFFFFFFFFu, acc.w, 16);

    if (slot == 0) {
        float4 b = ((const float4*)bias)[cg];
        float4 a = ((const float4*)prelu_a)[cg];
        float4 r;
        r.x = acc.x + b.x; r.x = r.x > 0.f ? r.x : a.x * r.x;
        r.y = acc.y + b.y; r.y = r.y > 0.f ? r.y : a.y * r.y;
        r.z = acc.z + b.z; r.z = r.z > 0.f ? r.z : a.z * r.z;
        r.w = acc.w + b.w; r.w = r.w > 0.f ? r.w : a.w * r.w;
        ((float4*)(out + (size_t)warp * HID_CH))[cg] = r;
    }
}

// ---------------------------------------------------------------------------
extern "C" void kernel_launch(void* const* d_in, const int* in_sizes, int n_in,
                              void* d_out, int out_size) {
    const float* x     = (const float*)d_in[0];
    const int*   ei    = (const int*)d_in[1];
    const float* W     = (const float*)d_in[2];
    const float* bias  = (const float*)d_in[3];
    const float* prelu = (const float*)d_in[4];
    float*       out   = (float*)d_out;

    cudaFuncSetAttribute(gemm_mma_kernel, cudaFuncAttributeMaxDynamicSharedMemorySize,
                         GEMM_SMEM_BYTES);

    convert_w_kernel<<<(IN_CH * HID_CH + 255) / 256, 256>>>(W);

    int gemm_blocks = (N_NODES + 127) / 128;
    gemm_mma_kernel<<<gemm_blocks, 256, GEMM_SMEM_BYTES>>>(x);

    zero_kernel<<<(NBINS + 255) / 256, 256>>>();
    hist_kernel<<<(N_EDGES / 4 + 255) / 256, 256>>>(ei);
    scan_a_kernel<<<SCAN_BLOCKS, 256>>>();
    scan_b_kernel<<<1, 256>>>();
    scan_c_kernel<<<SCAN_BLOCKS, 256>>>();
    reorder_kernel<<<(N_EDGES / 4 + 255) / 256, 256>>>(ei);

    int gather_blocks = (N_NODES * 32 + 255) / 256;
    gather_kernel<<<gather_blocks, 256>>>(bias, prelu, out);
}